// round 1
// baseline (speedup 1.0000x reference)
#include <cuda_runtime.h>
#include <math.h>

// ---------------------------------------------------------------------------
// Problem constants
// ---------------------------------------------------------------------------
constexpr int B_  = 32;
constexpr int L_  = 256;
constexpr int D_  = 256;
constexpr int E_  = 32;
constexpr int H_  = 8;
constexpr int HD_ = 32;
constexpr float SCALE_ = 0.17677669529663687f;  // 1/sqrt(32)

constexpr int ROWS_ = B_ * L_;   // 8192

// ---------------------------------------------------------------------------
// Device scratch (static: no allocation allowed)
// ---------------------------------------------------------------------------
__device__ float g_qkv[ROWS_ * 3 * D_];   // [B*L, 768]  q|k|v
__device__ float g_aout[ROWS_ * D_];      // [B*L, 256]  attention output (pre out-proj)

// ---------------------------------------------------------------------------
// Kernel 1/3: C[m][n] = sum_k A[m][k] * W[n][k] + bias[n]   (A @ W^T + b)
// BM=BN=128, BK=16, 256 threads, 8x8 microtile. All dims divide exactly.
// ---------------------------------------------------------------------------
template<int BM, int BN, int BK>
__global__ __launch_bounds__(256)
void sgemm_nt_bias(const float* __restrict__ A, const float* __restrict__ W,
                   const float* __restrict__ bias, float* __restrict__ C,
                   int M, int N, int K)
{
    __shared__ float As[BK][BM + 4];
    __shared__ float Bs[BK][BN + 4];

    const int tid = threadIdx.x;
    const int tx  = tid & 15;          // 0..15 (n)
    const int ty  = tid >> 4;          // 0..15 (m)
    const int m0  = blockIdx.y * BM;
    const int n0  = blockIdx.x * BN;

    float acc[8][8];
#pragma unroll
    for (int i = 0; i < 8; i++)
#pragma unroll
        for (int j = 0; j < 8; j++) acc[i][j] = 0.f;

    for (int k0 = 0; k0 < K; k0 += BK) {
        // load A tile (BM x BK) transposed into As[k][m]
#pragma unroll
        for (int it = 0; it < (BM * BK) / (256 * 4); ++it) {
            int f4  = tid + it * 256;
            int row = f4 >> 2;
            int c4  = (f4 & 3) * 4;
            float4 v = *(const float4*)&A[(size_t)(m0 + row) * K + k0 + c4];
            As[c4 + 0][row] = v.x; As[c4 + 1][row] = v.y;
            As[c4 + 2][row] = v.z; As[c4 + 3][row] = v.w;
        }
        // load W tile (BN x BK) transposed into Bs[k][n]
#pragma unroll
        for (int it = 0; it < (BN * BK) / (256 * 4); ++it) {
            int f4  = tid + it * 256;
            int row = f4 >> 2;
            int c4  = (f4 & 3) * 4;
            float4 v = *(const float4*)&W[(size_t)(n0 + row) * K + k0 + c4];
            Bs[c4 + 0][row] = v.x; Bs[c4 + 1][row] = v.y;
            Bs[c4 + 2][row] = v.z; Bs[c4 + 3][row] = v.w;
        }
        __syncthreads();

#pragma unroll
        for (int kk = 0; kk < BK; ++kk) {
            float a[8], b[8];
            *(float4*)&a[0] = *(const float4*)&As[kk][ty * 8];
            *(float4*)&a[4] = *(const float4*)&As[kk][ty * 8 + 4];
            *(float4*)&b[0] = *(const float4*)&Bs[kk][tx * 8];
            *(float4*)&b[4] = *(const float4*)&Bs[kk][tx * 8 + 4];
#pragma unroll
            for (int i = 0; i < 8; i++)
#pragma unroll
                for (int j = 0; j < 8; j++)
                    acc[i][j] += a[i] * b[j];
        }
        __syncthreads();
    }

    // epilogue: add bias, write (vectorized; N % 4 == 0 guaranteed here)
#pragma unroll
    for (int i = 0; i < 8; i++) {
        int m = m0 + ty * 8 + i;
#pragma unroll
        for (int j4 = 0; j4 < 2; j4++) {
            int n = n0 + tx * 8 + j4 * 4;
            float4 o;
            o.x = acc[i][j4 * 4 + 0] + bias[n + 0];
            o.y = acc[i][j4 * 4 + 1] + bias[n + 1];
            o.z = acc[i][j4 * 4 + 2] + bias[n + 2];
            o.w = acc[i][j4 * 4 + 3] + bias[n + 3];
            *(float4*)&C[(size_t)m * N + n] = o;
        }
    }
}

// ---------------------------------------------------------------------------
// Kernel 2: fused edge attention.
// One CTA per (batch b, 16-query tile). 256 threads = 8 warps.
// Streams 16-key tiles. Per (q,k) pair one thread computes:
//   edge e/g projections, qk dots (8 heads), writes edge_out from raw scores.
// Then per-head warps do online softmax (gate in numerator only) + AV.
// ---------------------------------------------------------------------------
constexpr int QT = 16;
constexpr int KT = 16;
constexpr int KVSTR = D_ + 4;   // padded row stride for q/k/v tiles

struct AttnSmem {
    float q[QT][KVSTR];
    float k[KT][KVSTR];
    float v[KT][KVSTR];
    float s[H_][QT][KT + 1];   // raw scores, overwritten with p*g in phase B
    float g[H_][QT][KT + 1];   // sigmoid gate
    float m[H_][QT];
    float z[H_][QT];
    float r[H_][QT];
    float ew[H_][E_];
    float gw[H_][E_];
    float eow[E_][H_];
    float eb[H_];
    float gb[H_];
    float eob[E_];
};

__global__ __launch_bounds__(256)
void edge_attn_kernel(const float* __restrict__ edge_x,
                      const float* __restrict__ e_w, const float* __restrict__ e_b,
                      const float* __restrict__ g_w, const float* __restrict__ g_b,
                      const float* __restrict__ eo_w, const float* __restrict__ eo_b,
                      float* __restrict__ edge_out)
{
    extern __shared__ char smem_raw[];
    AttnSmem& sm = *reinterpret_cast<AttnSmem*>(smem_raw);

    const int tid = threadIdx.x;
    const int b   = blockIdx.y;
    const int q0  = blockIdx.x * QT;

    // --- load weights / init state ---
    {
        // H_*E_ == 256 == blockDim.x
        ((float*)sm.ew)[tid]  = e_w[tid];
        ((float*)sm.gw)[tid]  = g_w[tid];
        ((float*)sm.eow)[tid] = eo_w[tid];
        if (tid < H_) { sm.eb[tid] = e_b[tid]; sm.gb[tid] = g_b[tid]; }
        if (tid < E_) { sm.eob[tid] = eo_b[tid]; }
        if (tid < H_ * QT) {
            ((float*)sm.m)[tid] = -1e30f;
            ((float*)sm.z)[tid] = 0.f;
        }
    }
    // --- load q tile: 16 rows x 256 floats from g_qkv[:, 0:256] ---
#pragma unroll
    for (int it = 0; it < 4; ++it) {
        int f4  = tid + it * 256;          // 0..1023
        int row = f4 >> 6;
        int c   = (f4 & 63) * 4;
        *(float4*)&sm.q[row][c] =
            *(const float4*)&g_qkv[((size_t)(b * L_) + q0 + row) * (3 * D_) + c];
    }
    __syncthreads();

    const int qi   = tid >> 4;   // 0..15 query within tile (phase A)
    const int kk   = tid & 15;   // 0..15 key within tile   (phase A)
    const int h    = tid >> 5;   // 0..7 head (phase B)
    const int lane = tid & 31;

    float acc[QT];
#pragma unroll
    for (int i = 0; i < QT; i++) acc[i] = 0.f;

    for (int k0 = 0; k0 < L_; k0 += KT) {
        // --- stage k/v tiles ---
#pragma unroll
        for (int it = 0; it < 4; ++it) {
            int f4  = tid + it * 256;
            int row = f4 >> 6;
            int c   = (f4 & 63) * 4;
            size_t base = ((size_t)(b * L_) + k0 + row) * (3 * D_);
            *(float4*)&sm.k[row][c] = *(const float4*)&g_qkv[base + D_ + c];
            *(float4*)&sm.v[row][c] = *(const float4*)&g_qkv[base + 2 * D_ + c];
        }
        __syncthreads();

        // --- Phase A: per (q,k) pair — edge proj, scores, gate, edge_out ---
        {
            const int j = k0 + kk;
            const float* ep =
                edge_x + (((size_t)(b * L_ + q0 + qi)) * L_ + j) * E_;
            float ev[E_];
#pragma unroll
            for (int c4 = 0; c4 < 8; c4++) {
                float4 t = *(const float4*)&ep[c4 * 4];
                ev[c4 * 4 + 0] = t.x; ev[c4 * 4 + 1] = t.y;
                ev[c4 * 4 + 2] = t.z; ev[c4 * 4 + 3] = t.w;
            }
            float sh[H_];
#pragma unroll
            for (int hh = 0; hh < H_; ++hh) {
                float ea = sm.eb[hh];
                float ga = sm.gb[hh];
#pragma unroll
                for (int c = 0; c < E_; c++) {
                    ea += ev[c] * sm.ew[hh][c];
                    ga += ev[c] * sm.gw[hh][c];
                }
                float dot = 0.f;
#pragma unroll
                for (int c4 = 0; c4 < 8; c4++) {
                    float4 qv = *(const float4*)&sm.q[qi][hh * HD_ + c4 * 4];
                    float4 kv = *(const float4*)&sm.k[kk][hh * HD_ + c4 * 4];
                    dot += qv.x * kv.x + qv.y * kv.y + qv.z * kv.z + qv.w * kv.w;
                }
                float sv = dot * SCALE_ + ea;
                sh[hh] = sv;
                sm.s[hh][qi][kk] = sv;
                sm.g[hh][qi][kk] = 1.0f / (1.0f + __expf(-ga));
            }
            // edge_out from RAW scores: [E] = sum_h s[h] * eo_w[c][h] + eo_b[c]
            float* eo = edge_out + (((size_t)(b * L_ + q0 + qi)) * L_ + j) * E_;
#pragma unroll
            for (int c4 = 0; c4 < 8; c4++) {
                float vals[4];
#pragma unroll
                for (int u = 0; u < 4; u++) {
                    int c = c4 * 4 + u;
                    float a2 = sm.eob[c];
#pragma unroll
                    for (int hh = 0; hh < H_; hh++)
                        a2 += sh[hh] * sm.eow[c][hh];
                    vals[u] = a2;
                }
                float4 o; o.x = vals[0]; o.y = vals[1]; o.z = vals[2]; o.w = vals[3];
                *(float4*)&eo[c4 * 4] = o;
            }
        }
        __syncthreads();

        // --- Phase B: per-head online softmax + gated AV ---
        if (lane < QT) {
            const int q = lane;
            float mold = sm.m[h][q];
            float tmax = -1e30f;
#pragma unroll
            for (int t = 0; t < KT; t++) tmax = fmaxf(tmax, sm.s[h][q][t]);
            float mnew = fmaxf(mold, tmax);
            float r    = __expf(mold - mnew);
            float zs   = 0.f;
#pragma unroll
            for (int t = 0; t < KT; t++) {
                float p = __expf(sm.s[h][q][t] - mnew);
                zs += p;                                   // Z is UNGATED
                sm.s[h][q][t] = p * sm.g[h][q][t];         // numerator gated
            }
            sm.z[h][q] = sm.z[h][q] * r + zs;
            sm.m[h][q] = mnew;
            sm.r[h][q] = r;
        }
        __syncwarp();
        {
            const int d = lane;
#pragma unroll
            for (int q = 0; q < QT; q++) {
                float a = acc[q] * sm.r[h][q];
#pragma unroll
                for (int t = 0; t < KT; t++)
                    a += sm.s[h][q][t] * sm.v[t][h * HD_ + d];
                acc[q] = a;
            }
        }
        __syncthreads();
    }

    // --- epilogue: write attention output (layout [B*L, 256]) ---
#pragma unroll
    for (int q = 0; q < QT; q++) {
        g_aout[((size_t)(b * L_ + q0 + q)) * D_ + h * HD_ + lane] =
            acc[q] / sm.z[h][q];
    }
}

// ---------------------------------------------------------------------------
// kernel_launch
// ---------------------------------------------------------------------------
extern "C" void kernel_launch(void* const* d_in, const int* in_sizes, int n_in,
                              void* d_out, int out_size)
{
    const float* x       = (const float*)d_in[0];
    const float* edge_x  = (const float*)d_in[1];
    const float* in_w    = (const float*)d_in[2];
    const float* in_b    = (const float*)d_in[3];
    const float* out_w   = (const float*)d_in[4];
    const float* out_b   = (const float*)d_in[5];
    const float* e_w     = (const float*)d_in[6];
    const float* e_b     = (const float*)d_in[7];
    const float* g_w     = (const float*)d_in[8];
    const float* g_b     = (const float*)d_in[9];
    const float* eo_w    = (const float*)d_in[10];
    const float* eo_b    = (const float*)d_in[11];

    float* out0     = (float*)d_out;                      // [B, L, D]
    float* edge_out = out0 + (size_t)B_ * L_ * D_;        // [B, L, L, E]

    float* qkv_ptr  = nullptr;
    float* aout_ptr = nullptr;
    cudaGetSymbolAddress((void**)&qkv_ptr,  g_qkv);
    cudaGetSymbolAddress((void**)&aout_ptr, g_aout);

    const int smem_bytes = (int)sizeof(AttnSmem);
    cudaFuncSetAttribute(edge_attn_kernel,
                         cudaFuncAttributeMaxDynamicSharedMemorySize, smem_bytes);

    // 1) qkv = x @ in_proj_w^T + b   -> g_qkv [8192, 768]
    sgemm_nt_bias<128, 128, 16><<<dim3(3 * D_ / 128, ROWS_ / 128), 256>>>(
        x, in_w, in_b, qkv_ptr, ROWS_, 3 * D_, D_);

    // 2) fused edge attention -> g_aout, edge_out
    edge_attn_kernel<<<dim3(L_ / QT, B_), 256, smem_bytes>>>(
        edge_x, e_w, e_b, g_w, g_b, eo_w, eo_b, edge_out);

    // 3) out = aout @ out_w^T + out_b -> d_out[0 : B*L*D]
    sgemm_nt_bias<128, 128, 16><<<dim3(D_ / 128, ROWS_ / 128), 256>>>(
        aout_ptr, out_w, out_b, out0, ROWS_, D_, D_);
}